// round 16
// baseline (speedup 1.0000x reference)
#include <cuda_runtime.h>
#include <math.h>

#define BATCH 8192
#define NKNOT 2000
#define NI    1999
#define NT    500
#define NH1   50
#define NH2   10
#define CSZ   17
#define NCH   118            // 117*17 = 1989, last chunk = 11 elems

// spline smem layout (floats)
#define PSTR      4004
#define SKD_OFF   (2 * PSTR)
#define SEV_OFF   (4 * PSTR)
#define SPJ_OFF   (SEV_OFF + 4 * NT)
#define SCR_OFF   (SPJ_OFF + NT)          // 18516: 16 ull exchange scratch
#define SMEM_SPL_FL (SCR_OFF + 32)        // 18548 -> 74,192 B (3 blocks/SM)

// MLP v8: 56 rows/block, grid 147, 1024 threads, 4-row x 10-k tiles
#define MROWS 56
#define NGRP  14
#define GSTR  2020
#define NSEG  14
#define TILES 70                           // 14 row-groups x 5 k-tiles(10)
#define ACTIVE_MLP (TILES * NSEG)          // 980
#define JLEN  36                           // 14*36 = 504 >= 500
#define PPU   (MROWS * 25)                 // 1400 ull partials per seg
#define NGROUPS_PAD 2058
#define ACT_FL     (NGRP * GSTR)           // 28280
#define W1_OFF     ACT_FL
#define W1_FL      (NT * NH1)              // 25000
#define CONST_OFF  (W1_OFF + W1_FL)        // 53280
#define SMEM_MLP_FL (CONST_OFF + 576)      // 53856 -> 215,424 B
#define SH1_OFF    (NSEG * PPU * 2)        // 39200 (after ull partials)
#define SH2_OFF    (SH1_OFF + 2800)        // 42000

__constant__ float CP_TAB[8] = {
    0.5f, 0.28571429f, 0.26923077f, 0.26804124f,
    0.26795580f, 0.26794967f, 0.26794923f, 0.26794919f
};
#define CSTAR  0.26794919f
#define ELAST  0.57735027f
#define PW     5997.0f
#define WGC    (PW * CSTAR)
#define WGL    (PW * ELAST)

typedef unsigned long long ull;

__device__ float g_out[(size_t)NGROUPS_PAD * 2000];   // blocked [group][500 j][4 rows]

__device__ __forceinline__ ull f2fma(ull a, ull b, ull c) {
    ull d; asm("fma.rn.f32x2 %0, %1, %2, %3;" : "=l"(d) : "l"(a), "l"(b), "l"(c)); return d;
}
__device__ __forceinline__ ull f2mul(ull a, ull b) {
    ull d; asm("mul.rn.f32x2 %0, %1, %2;" : "=l"(d) : "l"(a), "l"(b)); return d;
}
__device__ __forceinline__ ull f2add(ull a, ull b) {
    ull d; asm("add.rn.f32x2 %0, %1, %2;" : "=l"(d) : "l"(a), "l"(b)); return d;
}
__device__ __forceinline__ ull splat(float w) {
    ull r; asm("mov.b64 %0, {%1, %1};" : "=l"(r) : "f"(w)); return r;
}
__device__ __forceinline__ void unpack2(ull v, float& lo, float& hi) {
    asm("mov.b64 {%0, %1}, %2;" : "=f"(lo), "=f"(hi) : "l"(v));
}
__device__ __forceinline__ float tknot(int i) {
    return (i >= NI) ? 1.0f : (float)i * (1.0f / 1999.0f);
}

// =================== K1: spline solve (halo-free exchange) + evaluate ========
__global__ __launch_bounds__(256, 3)
void spline_kernel(const float* __restrict__ x, const float* __restrict__ raw_index) {
    extern __shared__ float sm[];
    float*  sxp  = sm;
    float*  skdp = sm + SKD_OFF;
    float4* sev  = (float4*)(sm + SEV_OFF);
    int*    spj  = (int*)(sm + SPJ_OFF);
    ull*    scrA = (ull*)(sm + SCR_OFF);
    ull*    scrB = scrA + 8;
    const int b0   = blockIdx.x * 4;
    const int tid  = threadIdx.x;
    const int lane = tid & 31;
    const int wrp  = tid >> 5;

    // ---- staging loads (register-staged) ----
    float4 va[4], vb[4];
    int pidx[4], qidx[4];
    #pragma unroll
    for (int k = 0; k < 4; k++) {
        int it = tid + k * 256;
        if (it < 1000) {
            int pr = it / 500, q = it - pr * 500;
            pidx[k] = pr; qidx[k] = q;
            va[k] = ((const float4*)(x + (size_t)(b0 + 2 * pr)     * NKNOT))[q];
            vb[k] = ((const float4*)(x + (size_t)(b0 + 2 * pr + 1) * NKNOT))[q];
        } else pidx[k] = -1;
    }

    // ---- eval-point preprocessing under LDG latency ----
    for (int j = tid; j < NT; j += 256) {
        float z = raw_index[j];
        float t = 1.0f / (1.0f + expf(-z));
        int p = (int)(t * 1999.0f);
        if (p < 0) p = 0;
        if (p > 1998) p = 1998;
        while (p < 1998 && tknot(p + 1) < t) p++;
        while (p > 0 && tknot(p) >= t) p--;
        float tp  = tknot(p);
        float Hh  = tknot(p + 1) - tp;
        float u   = (t - tp) / Hh;
        float cb  = u * u * (3.0f - 2.0f * u);
        float omu = 1.0f - u;
        float4 c;
        c.x = 1.0f - cb;
        c.y = cb;
        c.z = Hh * u * omu * omu;
        c.w = Hh * u * u * (u - 1.0f);
        spj[j] = p;
        sev[j] = c;
    }

    #pragma unroll
    for (int k = 0; k < 4; k++) {
        if (pidx[k] >= 0) {
            float4 a = va[k], b = vb[k];
            float4* d = (float4*)(sxp + pidx[k] * PSTR + qidx[k] * 8);
            d[0] = make_float4(a.x, b.x, a.y, b.y);
            d[1] = make_float4(a.z, b.z, a.w, b.w);
        }
    }
    __syncthreads();

    // ---- solve: 236 active threads, zero-inflow chunks + neighbor exchange --
    const bool act = tid < 2 * NCH;
    const ull NEG1 = splat(-1.0f);
    const ull CW   = splat(WGC);
    const ull CN   = splat(-CSTAR);

    int pr = 0, ch = 0, c0 = 0;
    const ull* X = (const ull*)sxp;
    ull*       K = (ull*)skdp;
    ull kreg[CSZ];
    ull dp = 0ULL;

    if (act) {
        pr = (tid >= NCH) ? 1 : 0;
        ch = tid - pr * NCH;
        c0 = ch * CSZ;
        X = (const ull*)(sxp  + pr * PSTR);
        K = (ull*)      (skdp + pr * PSTR);

        if (ch == 0) {
            ull pp = 0ULL, xc = X[0];
            #pragma unroll
            for (int i = 0; i < CSZ; i++) {
                ull xp = X[i + 1];
                ull pc = f2mul(f2fma(xc, NEG1, xp), splat(PW));
                ull s  = f2add(pp, pc);
                if (i == 0) dp = f2mul(s, splat(0.5f));
                else        dp = f2mul(f2fma(dp, NEG1, s), splat((i < 8) ? CP_TAB[i] : CSTAR));
                kreg[i] = dp;
                pp = pc; xc = xp;
            }
        } else if (ch < 117) {
            ull xm = X[c0 - 1], xc = X[c0];
            #pragma unroll
            for (int k = 0; k < CSZ; k++) {
                ull xp = X[c0 + k + 1];
                dp = f2fma(dp, CN, f2mul(f2fma(xm, NEG1, xp), CW));
                kreg[k] = dp;
                xm = xc; xc = xp;
            }
        } else {
            ull xm = X[1988], xc = X[1989];
            #pragma unroll
            for (int k = 0; k < 10; k++) {
                ull xp = X[1990 + k];
                dp = f2fma(dp, CN, f2mul(f2fma(xm, NEG1, xp), CW));
                kreg[k] = dp;
                xm = xc; xc = xp;
            }
            dp = f2fma(dp, splat(-ELAST), f2mul(f2fma(xm, NEG1, xc), splat(WGL)));
            kreg[10] = dp;
        }
    }

    if (act && lane == 31) scrA[wrp] = dp;
    __syncthreads();
    ull dp_in = __shfl_up_sync(0xffffffffu, dp, 1);
    if (lane == 0 && wrp > 0) dp_in = scrA[wrp - 1];
    if (ch == 0) dp_in = 0ULL;

    if (act && ch > 0) {
        ull corr = dp_in;
        if (ch < 117) {
            #pragma unroll
            for (int k = 0; k < 12; k++) { corr = f2mul(corr, CN); kreg[k] = f2add(kreg[k], corr); }
        } else {
            #pragma unroll
            for (int k = 0; k < 10; k++) { corr = f2mul(corr, CN); kreg[k] = f2add(kreg[k], corr); }
            corr = f2mul(corr, splat(-ELAST));
            kreg[10] = f2add(kreg[10], corr);
        }
    }

    ull xn = 0ULL;
    if (act) {
        if (ch == 117) {
            xn = kreg[10];
            K[NI] = xn;
            #pragma unroll
            for (int k = 9; k >= 0; k--) { xn = f2fma(xn, CN, kreg[k]); K[1989 + k] = xn; }
        } else if (ch == 0) {
            #pragma unroll
            for (int i = CSZ - 1; i >= 0; i--) {
                xn = f2fma(xn, splat(-((i < 8) ? CP_TAB[i] : CSTAR)), kreg[i]);
                kreg[i] = xn;
            }
        } else {
            #pragma unroll
            for (int k = CSZ - 1; k >= 0; k--) { xn = f2fma(xn, CN, kreg[k]); kreg[k] = xn; }
        }
    }

    if (act && lane == 0) scrB[wrp] = xn;
    __syncthreads();
    ull xn_in = __shfl_down_sync(0xffffffffu, xn, 1);
    if (lane == 31 && wrp < 7) xn_in = scrB[wrp + 1];

    if (act && ch < 117) {
        ull corr = xn_in;
        #pragma unroll
        for (int k = CSZ - 1; k >= 5; k--) { corr = f2mul(corr, CN); kreg[k] = f2add(kreg[k], corr); }
        #pragma unroll
        for (int k = 0; k < CSZ; k++) K[c0 + k] = kreg[k];
    }
    __syncthreads();

    // ---- evaluate: 1000 f32x2 items ----
    float* ob = g_out + (size_t)blockIdx.x * (4 * NT);
    #pragma unroll
    for (int k = 0; k < 4; k++) {
        int it = tid + k * 256;
        if (it < 1000) {
            int j  = it >> 1;
            int p2 = it & 1;
            int    p = spj[j];
            float4 c = sev[j];
            const ull* Xe = (const ull*)(sxp  + p2 * PSTR);
            const ull* Ke = (const ull*)(skdp + p2 * PSTR);
            ull r = f2mul(Xe[p], splat(c.x));
            r = f2fma(Xe[p + 1], splat(c.y), r);
            r = f2fma(Ke[p],     splat(c.z), r);
            r = f2fma(Ke[p + 1], splat(c.w), r);
            *(ull*)(ob + it * 2) = r;
        }
    }
}

// =================== K2: MLP v8 (1024 threads, 4-row x 10-k tiles) ===========
__global__ __launch_bounds__(1024, 1)
void mlp_kernel(const float* __restrict__ W1, const float* __restrict__ b1,
                const float* __restrict__ W2, const float* __restrict__ b2,
                const float* __restrict__ W3, const float* __restrict__ b3,
                float* __restrict__ out) {
    extern __shared__ float sm[];
    float* sact = sm;                    // 14 groups x 2020 (group-major [g][j][4])
    float* sw1  = sm + W1_OFF;           // dense W1 [j][50]
    float* scst = sm + CONST_OFF;
    const int tid = threadIdx.x;
    const int b   = blockIdx.x;

    // stage activations: 7000 float4, straight copy
    {
        const float4* src = (const float4*)g_out + (size_t)b * NGRP * NT;
        #pragma unroll
        for (int k = 0; k < 7; k++) {
            int i = tid + k * 1024;
            if (i < NGRP * NT) {
                int g = i / NT, p = i - g * NT;
                *(float4*)(sact + g * GSTR + p * 4) = src[i];
            }
        }
    }
    // stage W1 dense: 6250 float4
    {
        const float4* w4 = (const float4*)W1;
        #pragma unroll
        for (int k = 0; k < 7; k++) {
            int i = tid + k * 1024;
            if (i < W1_FL / 4) *(float4*)(sw1 + i * 4) = w4[i];
        }
    }
    if (tid < NH1 * NH2) scst[tid] = W2[tid];
    if (tid < NH1) scst[500 + tid] = b1[tid];
    if (tid < NH2) scst[550 + tid] = b2[tid];
    if (tid < NH2) scst[560 + tid] = W3[tid];
    if (tid == 0)  scst[570] = b3[0];
    __syncthreads();

    // ---- layer 1: 4 rows x 10 k per thread; 980 active, 32 warps/SM ----
    ull acc[4][5] = {};
    const bool active = tid < ACTIVE_MLP;
    int g = 0, kt = 0, seg = 0;
    if (active) {
        seg = tid / TILES;
        int tile = tid - seg * TILES;
        kt = tile % 5;             // 5 distinct weight addrs per warp -> broadcast
        g  = tile / 5;             // row-group 0..13 (<=7 distinct per warp, dg<8 -> CF)
        int j0 = seg * JLEN;
        int j1 = min(j0 + JLEN, NT);
        const float* A  = sact + g * GSTR;
        const float* wb = sw1 + kt * 10;
        #pragma unroll 2
        for (int j = j0; j < j1; j++) {
            float4 a = *(const float4*)(A + 4 * j);
            const ull* w = (const ull*)(wb + j * NH1);   // 8B-aligned (kt*10+j*50 even)
            ull w0 = w[0], w1 = w[1], w2 = w[2], w3 = w[3], w4 = w[4];
            ull s0 = splat(a.x), s1 = splat(a.y), s2 = splat(a.z), s3 = splat(a.w);
            #pragma unroll
            for (int q = 0; q < 5; q++) {
                ull wq = (q == 0) ? w0 : (q == 1) ? w1 : (q == 2) ? w2 : (q == 3) ? w3 : w4;
                acc[0][q] = f2fma(s0, wq, acc[0][q]);
                acc[1][q] = f2fma(s1, wq, acc[1][q]);
                acc[2][q] = f2fma(s2, wq, acc[2][q]);
                acc[3][q] = f2fma(s3, wq, acc[3][q]);
            }
        }
    }
    __syncthreads();   // act + W1 regions now dead

    // partials as packed ull: [seg][56 rows][25 kpairs]
    ull* su = (ull*)sm;
    if (active) {
        #pragma unroll
        for (int r = 0; r < 4; r++) {
            int row = 4 * g + r;
            #pragma unroll
            for (int q = 0; q < 5; q++)
                su[seg * PPU + row * 25 + kt * 5 + q] = acc[r][q];
        }
    }
    __syncthreads();

    // reduce 14 partials (packed) + bias + leaky -> sh1
    float* sh1 = sm + SH1_OFF;
    #pragma unroll
    for (int k = 0; k < 2; k++) {
        int i = tid + k * 1024;
        if (i < PPU) {
            ull s = su[i];
            #pragma unroll
            for (int q = 1; q < NSEG; q++) s = f2add(s, su[q * PPU + i]);
            int row = i / 25, kp = i - row * 25;
            float lo, hi;
            unpack2(s, lo, hi);
            float h0 = lo + scst[500 + 2 * kp];
            float h1 = hi + scst[500 + 2 * kp + 1];
            sh1[row * NH1 + 2 * kp]     = (h0 >= 0.0f) ? h0 : 0.01f * h0;
            sh1[row * NH1 + 2 * kp + 1] = (h1 >= 0.0f) ? h1 : 0.01f * h1;
        }
    }
    __syncthreads();

    // layer 2: 560 outputs
    float* sh2 = sm + SH2_OFF;
    if (tid < MROWS * NH2) {
        int r = tid / NH2, kk = tid - r * NH2;
        float a = scst[550 + kk];
        #pragma unroll
        for (int q = 0; q < NH1; q++)
            a = fmaf(sh1[r * NH1 + q], scst[q * NH2 + kk], a);
        sh2[tid] = (a >= 0.0f) ? a : 0.01f * a;
    }
    __syncthreads();

    // layer 3 (guarded for the padded tail block)
    if (tid < MROWS) {
        int row = b * MROWS + tid;
        if (row < BATCH) {
            float a = scst[570];
            #pragma unroll
            for (int i = 0; i < NH2; i++)
                a = fmaf(sh2[tid * NH2 + i], scst[560 + i], a);
            out[row] = a;
        }
    }
}

// =================== launch ===================================================
extern "C" void kernel_launch(void* const* d_in, const int* in_sizes, int n_in,
                              void* d_out, int out_size) {
    const float* x  = (const float*)d_in[0];
    const float* ri = (const float*)d_in[1];
    const float* W1 = (const float*)d_in[2];
    const float* b1 = (const float*)d_in[3];
    const float* W2 = (const float*)d_in[4];
    const float* b2 = (const float*)d_in[5];
    const float* W3 = (const float*)d_in[6];
    const float* b3 = (const float*)d_in[7];
    float* out = (float*)d_out;

    size_t smem1 = (size_t)SMEM_SPL_FL * sizeof(float);   // 74,192 B
    size_t smem2 = (size_t)SMEM_MLP_FL * sizeof(float);   // 215,424 B
    cudaFuncSetAttribute(spline_kernel, cudaFuncAttributeMaxDynamicSharedMemorySize, (int)smem1);
    cudaFuncSetAttribute(mlp_kernel,    cudaFuncAttributeMaxDynamicSharedMemorySize, (int)smem2);

    spline_kernel<<<BATCH / 4, 256, smem1>>>(x, ri);
    mlp_kernel<<<(BATCH + MROWS - 1) / MROWS, 1024, smem2>>>(W1, b1, W2, b2, W3, b3, out);
}

// round 17
// speedup vs baseline: 1.0624x; 1.0624x over previous
#include <cuda_runtime.h>
#include <math.h>

#define BATCH 8192
#define NKNOT 2000
#define NI    1999
#define NT    500
#define NH1   50
#define NH2   10
#define CSZ   17
#define NCH   118            // 117*17 = 1989, last chunk = 11 elems

// spline smem layout (floats)
#define PSTR      4004
#define SKD_OFF   (2 * PSTR)
#define SEV_OFF   (4 * PSTR)
#define SPJ_OFF   (SEV_OFF + 4 * NT)
#define SCR_OFF   (SPJ_OFF + NT)          // 18516: 16 ull exchange scratch
#define SMEM_SPL_FL (SCR_OFF + 32)        // 18548 -> 74,192 B (3 blocks/SM)

// MLP v6.1 (R13 config): 56 rows/block, grid 147, 512 threads, 8-row x 10-k tiles
#define MROWS 56
#define NGRP  14
#define GSTR  2020
#define NSEG  14
#define TILES 35                           // 7 row-octets x 5 k-tiles(10)
#define ACTIVE_MLP (TILES * NSEG)          // 490
#define JLEN  36                           // 14*36 = 504 >= 500
#define PPU   (MROWS * 25)                 // 1400 ull partials per seg
#define NGROUPS_PAD 2058
#define ACT_FL     (NGRP * GSTR)           // 28280
#define W1_OFF     ACT_FL
#define W1_FL      (NT * NH1)              // 25000
#define CONST_OFF  (W1_OFF + W1_FL)        // 53280
#define SMEM_MLP_FL (CONST_OFF + 576)      // 53856 -> 215,424 B
#define SH1_OFF    (NSEG * PPU * 2)        // 39200 (after ull partials)
#define SH2_OFF    (SH1_OFF + 2800)        // 42000

__constant__ float CP_TAB[8] = {
    0.5f, 0.28571429f, 0.26923077f, 0.26804124f,
    0.26795580f, 0.26794967f, 0.26794923f, 0.26794919f
};
#define CSTAR  0.26794919f
#define ELAST  0.57735027f
#define PW     5997.0f
#define WGC    (PW * CSTAR)
#define WGL    (PW * ELAST)

typedef unsigned long long ull;

__device__ float g_out[(size_t)NGROUPS_PAD * 2000];   // blocked [group][500 j][4 rows]

__device__ __forceinline__ ull f2fma(ull a, ull b, ull c) {
    ull d; asm("fma.rn.f32x2 %0, %1, %2, %3;" : "=l"(d) : "l"(a), "l"(b), "l"(c)); return d;
}
__device__ __forceinline__ ull f2mul(ull a, ull b) {
    ull d; asm("mul.rn.f32x2 %0, %1, %2;" : "=l"(d) : "l"(a), "l"(b)); return d;
}
__device__ __forceinline__ ull f2add(ull a, ull b) {
    ull d; asm("add.rn.f32x2 %0, %1, %2;" : "=l"(d) : "l"(a), "l"(b)); return d;
}
__device__ __forceinline__ ull splat(float w) {
    ull r; asm("mov.b64 %0, {%1, %1};" : "=l"(r) : "f"(w)); return r;
}
__device__ __forceinline__ void unpack2(ull v, float& lo, float& hi) {
    asm("mov.b64 {%0, %1}, %2;" : "=f"(lo), "=f"(hi) : "l"(v));
}
__device__ __forceinline__ float tknot(int i) {
    return (i >= NI) ? 1.0f : (float)i * (1.0f / 1999.0f);
}

// =================== K1: spline solve (halo-free exchange) + evaluate ========
__global__ __launch_bounds__(256, 3)
void spline_kernel(const float* __restrict__ x, const float* __restrict__ raw_index) {
    extern __shared__ float sm[];
    float*  sxp  = sm;
    float*  skdp = sm + SKD_OFF;
    float4* sev  = (float4*)(sm + SEV_OFF);
    int*    spj  = (int*)(sm + SPJ_OFF);
    ull*    scrA = (ull*)(sm + SCR_OFF);
    ull*    scrB = scrA + 8;
    const int b0   = blockIdx.x * 4;
    const int tid  = threadIdx.x;
    const int lane = tid & 31;
    const int wrp  = tid >> 5;

    // ---- staging loads (register-staged) ----
    float4 va[4], vb[4];
    int pidx[4], qidx[4];
    #pragma unroll
    for (int k = 0; k < 4; k++) {
        int it = tid + k * 256;
        if (it < 1000) {
            int pr = it / 500, q = it - pr * 500;
            pidx[k] = pr; qidx[k] = q;
            va[k] = ((const float4*)(x + (size_t)(b0 + 2 * pr)     * NKNOT))[q];
            vb[k] = ((const float4*)(x + (size_t)(b0 + 2 * pr + 1) * NKNOT))[q];
        } else pidx[k] = -1;
    }

    // ---- eval-point preprocessing under LDG latency ----
    for (int j = tid; j < NT; j += 256) {
        float z = raw_index[j];
        float t = 1.0f / (1.0f + expf(-z));
        int p = (int)(t * 1999.0f);
        if (p < 0) p = 0;
        if (p > 1998) p = 1998;
        while (p < 1998 && tknot(p + 1) < t) p++;
        while (p > 0 && tknot(p) >= t) p--;
        float tp  = tknot(p);
        float Hh  = tknot(p + 1) - tp;
        float u   = (t - tp) / Hh;
        float cb  = u * u * (3.0f - 2.0f * u);
        float omu = 1.0f - u;
        float4 c;
        c.x = 1.0f - cb;
        c.y = cb;
        c.z = Hh * u * omu * omu;
        c.w = Hh * u * u * (u - 1.0f);
        spj[j] = p;
        sev[j] = c;
    }

    #pragma unroll
    for (int k = 0; k < 4; k++) {
        if (pidx[k] >= 0) {
            float4 a = va[k], b = vb[k];
            float4* d = (float4*)(sxp + pidx[k] * PSTR + qidx[k] * 8);
            d[0] = make_float4(a.x, b.x, a.y, b.y);
            d[1] = make_float4(a.z, b.z, a.w, b.w);
        }
    }
    __syncthreads();

    // ---- solve: 236 active threads, zero-inflow chunks + neighbor exchange --
    const bool act = tid < 2 * NCH;
    const ull NEG1 = splat(-1.0f);
    const ull CW   = splat(WGC);
    const ull CN   = splat(-CSTAR);

    int pr = 0, ch = 0, c0 = 0;
    const ull* X = (const ull*)sxp;
    ull*       K = (ull*)skdp;
    ull kreg[CSZ];
    ull dp = 0ULL;

    if (act) {
        pr = (tid >= NCH) ? 1 : 0;
        ch = tid - pr * NCH;
        c0 = ch * CSZ;
        X = (const ull*)(sxp  + pr * PSTR);
        K = (ull*)      (skdp + pr * PSTR);

        if (ch == 0) {
            ull pp = 0ULL, xc = X[0];
            #pragma unroll
            for (int i = 0; i < CSZ; i++) {
                ull xp = X[i + 1];
                ull pc = f2mul(f2fma(xc, NEG1, xp), splat(PW));
                ull s  = f2add(pp, pc);
                if (i == 0) dp = f2mul(s, splat(0.5f));
                else        dp = f2mul(f2fma(dp, NEG1, s), splat((i < 8) ? CP_TAB[i] : CSTAR));
                kreg[i] = dp;
                pp = pc; xc = xp;
            }
        } else if (ch < 117) {
            ull xm = X[c0 - 1], xc = X[c0];
            #pragma unroll
            for (int k = 0; k < CSZ; k++) {
                ull xp = X[c0 + k + 1];
                dp = f2fma(dp, CN, f2mul(f2fma(xm, NEG1, xp), CW));
                kreg[k] = dp;
                xm = xc; xc = xp;
            }
        } else {
            ull xm = X[1988], xc = X[1989];
            #pragma unroll
            for (int k = 0; k < 10; k++) {
                ull xp = X[1990 + k];
                dp = f2fma(dp, CN, f2mul(f2fma(xm, NEG1, xp), CW));
                kreg[k] = dp;
                xm = xc; xc = xp;
            }
            dp = f2fma(dp, splat(-ELAST), f2mul(f2fma(xm, NEG1, xc), splat(WGL)));
            kreg[10] = dp;
        }
    }

    if (act && lane == 31) scrA[wrp] = dp;
    __syncthreads();
    ull dp_in = __shfl_up_sync(0xffffffffu, dp, 1);
    if (lane == 0 && wrp > 0) dp_in = scrA[wrp - 1];
    if (ch == 0) dp_in = 0ULL;

    if (act && ch > 0) {
        ull corr = dp_in;
        if (ch < 117) {
            #pragma unroll
            for (int k = 0; k < 12; k++) { corr = f2mul(corr, CN); kreg[k] = f2add(kreg[k], corr); }
        } else {
            #pragma unroll
            for (int k = 0; k < 10; k++) { corr = f2mul(corr, CN); kreg[k] = f2add(kreg[k], corr); }
            corr = f2mul(corr, splat(-ELAST));
            kreg[10] = f2add(kreg[10], corr);
        }
    }

    ull xn = 0ULL;
    if (act) {
        if (ch == 117) {
            xn = kreg[10];
            K[NI] = xn;
            #pragma unroll
            for (int k = 9; k >= 0; k--) { xn = f2fma(xn, CN, kreg[k]); K[1989 + k] = xn; }
        } else if (ch == 0) {
            #pragma unroll
            for (int i = CSZ - 1; i >= 0; i--) {
                xn = f2fma(xn, splat(-((i < 8) ? CP_TAB[i] : CSTAR)), kreg[i]);
                kreg[i] = xn;
            }
        } else {
            #pragma unroll
            for (int k = CSZ - 1; k >= 0; k--) { xn = f2fma(xn, CN, kreg[k]); kreg[k] = xn; }
        }
    }

    if (act && lane == 0) scrB[wrp] = xn;
    __syncthreads();
    ull xn_in = __shfl_down_sync(0xffffffffu, xn, 1);
    if (lane == 31 && wrp < 7) xn_in = scrB[wrp + 1];

    if (act && ch < 117) {
        ull corr = xn_in;
        #pragma unroll
        for (int k = CSZ - 1; k >= 5; k--) { corr = f2mul(corr, CN); kreg[k] = f2add(kreg[k], corr); }
        #pragma unroll
        for (int k = 0; k < CSZ; k++) K[c0 + k] = kreg[k];
    }
    __syncthreads();

    // ---- evaluate: 1000 f32x2 items ----
    float* ob = g_out + (size_t)blockIdx.x * (4 * NT);
    #pragma unroll
    for (int k = 0; k < 4; k++) {
        int it = tid + k * 256;
        if (it < 1000) {
            int j  = it >> 1;
            int p2 = it & 1;
            int    p = spj[j];
            float4 c = sev[j];
            const ull* Xe = (const ull*)(sxp  + p2 * PSTR);
            const ull* Ke = (const ull*)(skdp + p2 * PSTR);
            ull r = f2mul(Xe[p], splat(c.x));
            r = f2fma(Xe[p + 1], splat(c.y), r);
            r = f2fma(Ke[p],     splat(c.z), r);
            r = f2fma(Ke[p + 1], splat(c.w), r);
            *(ull*)(ob + it * 2) = r;
        }
    }

    // PDL: signal this block's completion so the MLP can launch into the tail
    cudaTriggerProgrammaticLaunchCompletion();
}

// =================== K2: MLP v6.1 + PDL pre-staging ==========================
__global__ __launch_bounds__(512, 1)
void mlp_kernel(const float* __restrict__ W1, const float* __restrict__ b1,
                const float* __restrict__ W2, const float* __restrict__ b2,
                const float* __restrict__ W3, const float* __restrict__ b3,
                float* __restrict__ out) {
    extern __shared__ float sm[];
    float* sact = sm;                    // 14 groups x 2020
    float* sw1  = sm + W1_OFF;           // dense W1 [j][50]
    float* scst = sm + CONST_OFF;
    const int tid = threadIdx.x;
    const int b   = blockIdx.x;

    // --- pre-sync staging: W1 + constants (independent of spline output) ---
    {
        const float4* w4 = (const float4*)W1;
        #pragma unroll
        for (int k = 0; k < 13; k++) {
            int i = tid + k * 512;
            if (i < W1_FL / 4) *(float4*)(sw1 + i * 4) = w4[i];
        }
    }
    if (tid < NH1 * NH2) scst[tid] = W2[tid];
    if (tid < NH1) scst[500 + tid] = b1[tid];
    if (tid < NH2) scst[550 + tid] = b2[tid];
    if (tid < NH2) scst[560 + tid] = W3[tid];
    if (tid == 0)  scst[570] = b3[0];

    // --- wait for the spline grid to complete before touching g_out ---
    cudaGridDependencySynchronize();

    // stage activations: 7000 float4, straight copy
    {
        const float4* src = (const float4*)g_out + (size_t)b * NGRP * NT;
        #pragma unroll
        for (int k = 0; k < 14; k++) {
            int i = tid + k * 512;
            if (i < NGRP * NT) {
                int g = i / NT, p = i - g * NT;
                *(float4*)(sact + g * GSTR + p * 4) = src[i];
            }
        }
    }
    __syncthreads();

    // ---- layer 1: 8 rows x 10 k per thread; 490 active ----
    ull acc[8][5] = {};
    const bool active = tid < ACTIVE_MLP;
    int rt = 0, kt = 0, seg = 0;
    if (active) {
        seg = tid / TILES;
        int tile = tid - seg * TILES;
        kt = tile % 5;
        rt = tile / 5;
        int j0 = seg * JLEN;
        int j1 = min(j0 + JLEN, NT);
        const float* A0 = sact + (2 * rt)     * GSTR;
        const float* A1 = sact + (2 * rt + 1) * GSTR;
        const float* wb = sw1 + kt * 10;
        #pragma unroll 2
        for (int j = j0; j < j1; j++) {
            float4 a  = *(const float4*)(A0 + 4 * j);
            float4 bb = *(const float4*)(A1 + 4 * j);
            const ull* w = (const ull*)(wb + j * NH1);   // 8B-aligned (kt*10+j*50 even)
            ull w0 = w[0], w1 = w[1], w2 = w[2], w3 = w[3], w4 = w[4];
            ull s0 = splat(a.x),  s1 = splat(a.y),  s2 = splat(a.z),  s3 = splat(a.w);
            ull s4 = splat(bb.x), s5 = splat(bb.y), s6 = splat(bb.z), s7 = splat(bb.w);
            #pragma unroll
            for (int q = 0; q < 5; q++) {
                ull wq = (q == 0) ? w0 : (q == 1) ? w1 : (q == 2) ? w2 : (q == 3) ? w3 : w4;
                acc[0][q] = f2fma(s0, wq, acc[0][q]);
                acc[1][q] = f2fma(s1, wq, acc[1][q]);
                acc[2][q] = f2fma(s2, wq, acc[2][q]);
                acc[3][q] = f2fma(s3, wq, acc[3][q]);
                acc[4][q] = f2fma(s4, wq, acc[4][q]);
                acc[5][q] = f2fma(s5, wq, acc[5][q]);
                acc[6][q] = f2fma(s6, wq, acc[6][q]);
                acc[7][q] = f2fma(s7, wq, acc[7][q]);
            }
        }
    }
    __syncthreads();   // act + W1 regions now dead

    // partials as packed ull: [seg][56 rows][25 kpairs]
    ull* su = (ull*)sm;
    if (active) {
        #pragma unroll
        for (int r = 0; r < 8; r++) {
            int row = 8 * rt + r;
            #pragma unroll
            for (int q = 0; q < 5; q++)
                su[seg * PPU + row * 25 + kt * 5 + q] = acc[r][q];
        }
    }
    __syncthreads();

    // reduce 14 partials (packed) + bias + leaky -> sh1
    float* sh1 = sm + SH1_OFF;
    #pragma unroll
    for (int k = 0; k < 3; k++) {
        int i = tid + k * 512;
        if (i < PPU) {
            ull s = su[i];
            #pragma unroll
            for (int q = 1; q < NSEG; q++) s = f2add(s, su[q * PPU + i]);
            int row = i / 25, kp = i - row * 25;
            float lo, hi;
            unpack2(s, lo, hi);
            float h0 = lo + scst[500 + 2 * kp];
            float h1 = hi + scst[500 + 2 * kp + 1];
            sh1[row * NH1 + 2 * kp]     = (h0 >= 0.0f) ? h0 : 0.01f * h0;
            sh1[row * NH1 + 2 * kp + 1] = (h1 >= 0.0f) ? h1 : 0.01f * h1;
        }
    }
    __syncthreads();

    // layer 2: 560 outputs
    float* sh2 = sm + SH2_OFF;
    #pragma unroll
    for (int k = 0; k < 2; k++) {
        int i = tid + k * 512;
        if (i < MROWS * NH2) {
            int r = i / NH2, kk = i - r * NH2;
            float a = scst[550 + kk];
            #pragma unroll
            for (int q = 0; q < NH1; q++)
                a = fmaf(sh1[r * NH1 + q], scst[q * NH2 + kk], a);
            sh2[i] = (a >= 0.0f) ? a : 0.01f * a;
        }
    }
    __syncthreads();

    // layer 3 (guarded for the padded tail block)
    if (tid < MROWS) {
        int row = b * MROWS + tid;
        if (row < BATCH) {
            float a = scst[570];
            #pragma unroll
            for (int i = 0; i < NH2; i++)
                a = fmaf(sh2[tid * NH2 + i], scst[560 + i], a);
            out[row] = a;
        }
    }
}

// =================== launch ===================================================
extern "C" void kernel_launch(void* const* d_in, const int* in_sizes, int n_in,
                              void* d_out, int out_size) {
    const float* x  = (const float*)d_in[0];
    const float* ri = (const float*)d_in[1];
    const float* W1 = (const float*)d_in[2];
    const float* b1 = (const float*)d_in[3];
    const float* W2 = (const float*)d_in[4];
    const float* b2 = (const float*)d_in[5];
    const float* W3 = (const float*)d_in[6];
    const float* b3 = (const float*)d_in[7];
    float* out = (float*)d_out;

    size_t smem1 = (size_t)SMEM_SPL_FL * sizeof(float);   // 74,192 B
    size_t smem2 = (size_t)SMEM_MLP_FL * sizeof(float);   // 215,424 B
    cudaFuncSetAttribute(spline_kernel, cudaFuncAttributeMaxDynamicSharedMemorySize, (int)smem1);
    cudaFuncSetAttribute(mlp_kernel,    cudaFuncAttributeMaxDynamicSharedMemorySize, (int)smem2);

    spline_kernel<<<BATCH / 4, 256, smem1>>>(x, ri);

    // MLP launched with programmatic dependent launch: starts in spline's
    // drain tail, stages W1/consts, then gridDependencySynchronize()s
    // before reading g_out.
    cudaLaunchConfig_t cfg = {};
    cfg.gridDim  = dim3((BATCH + MROWS - 1) / MROWS);
    cfg.blockDim = dim3(512);
    cfg.dynamicSmemBytes = smem2;
    cfg.stream = 0;
    cudaLaunchAttribute at[1];
    at[0].id = cudaLaunchAttributeProgrammaticStreamSerialization;
    at[0].val.programmaticStreamSerializationAllowed = 1;
    cfg.attrs = at;
    cfg.numAttrs = 1;
    cudaLaunchKernelEx(&cfg, mlp_kernel, W1, b1, W2, b2, W3, b3, out);
}